// round 7
// baseline (speedup 1.0000x reference)
#include <cuda_runtime.h>

// Block-diagonal grouped conv2d: 64 groups, 4 in-ch -> 4 out-ch per group, 3x3, pad 1.
// x:   (32, 256, 128, 128) fp32, channel index = ci*64 + head
// w:   (64, 4, 4, 3, 3)          w[head][co][ci][ky][kx]
// b:   (64, 4)
// out: (32, 256, 128, 128) fp32, channel index = co*64 + head
//
// v7: 16 pixels/thread (weight-LDS amortized 2x), TY=16, 128 threads,
//     swizzle phys(c)=c+4*(c>>4) conflict-free for stride-16 threads,
//     shuffle edges only at octet-pair boundary, packed f32x2 FMA, 4 CTAs/SM.

#define TY 16
#define SROWS (TY + 2)               // 18
#define SROW_P 156                   // phys floats per row (max phys idx 155)
#define PLANE_P (SROWS * SROW_P)     // 2808
#define S_IN_FLOATS (4 * PLANE_P)    // 11232
#define THREADS 128
#define H 128
#define W 128
#define PLANE (H * W)
#define SMEM_BYTES ((S_IN_FLOATS + 2 * 144 + 4) * 4)

typedef unsigned long long u64;

__device__ __forceinline__ u64 pk(float lo, float hi) {
    u64 r; asm("mov.b64 %0, {%1, %2};" : "=l"(r) : "f"(lo), "f"(hi)); return r;
}
// d += a*b  (packed 2x fp32)
__device__ __forceinline__ void ffma2(u64 &d, u64 a, u64 b) {
    asm("fma.rn.f32x2 %0, %1, %2, %0;" : "+l"(d) : "l"(a), "l"(b));
}

union F4 { float4 f; ulonglong2 u; };

__global__ __launch_bounds__(THREADS, 4)
void bdconv_kernel(const float* __restrict__ x, const float* __restrict__ w,
                   const float* __restrict__ bias, float* __restrict__ out) {
    extern __shared__ __align__(16) float smem[];
    float* s_in   = smem;                        // [ci][r][phys-col]
    u64*   s_w    = (u64*)(smem + S_IN_FLOATS);  // [ci][ky][kx][co], dup halves
    float* s_bias = (float*)(s_w + 144);

    const int blk  = blockIdx.x;
    const int tile = blk & 7;           // 8 row-tiles of 16
    const int head = (blk >> 3) & 63;
    const int b    = blk >> 9;
    const int y0   = tile * TY;
    const int tid  = threadIdx.x;
    const int wrp  = tid >> 5;
    const int lane = tid & 31;

    // ---- stage weights (duplicated into f32x2 lanes) + bias ----
    for (int t = tid; t < 144; t += THREADS) {
        const int co  = t / 36;
        const int rem = t % 36;
        const int ci  = rem / 9;
        const int tt  = rem % 9;        // ky*3+kx
        const float wv = w[((head * 4 + co) * 4 + ci) * 9 + tt];
        s_w[(ci * 9 + tt) * 4 + co] = pk(wv, wv);
    }
    if (tid < 4) s_bias[tid] = bias[head * 4 + tid];

    // ---- stage input: 4 warps x 18 rows (72 = 4ci x 18 rows) ----
    // lane = 8p + t  ->  m = 4t + p, x0 = 4m, phys col = 20t + 4p
    // (each 8-lane phase covers 8 distinct bank-quads: 20t mod 32 distinct)
    {
        const int p  = lane >> 3;
        const int t8 = lane & 7;
        const int x0 = 16 * t8 + 4 * p;
        const int pc = 20 * t8 + 4 * p;
        const float* xb = x + ((long long)b * 256 + head) * PLANE;  // ci stride 64*PLANE
        #pragma unroll
        for (int k = 0; k < 18; k++) {
            const int rr = wrp + (k << 2);            // 0..71
            const int ci = rr / SROWS;
            const int r  = rr - ci * SROWS;
            const int y  = y0 - 1 + r;
            float4 v = make_float4(0.f, 0.f, 0.f, 0.f);
            if (y >= 0 && y < H)
                v = *(const float4*)(xb + ci * (64 * PLANE) + y * W + x0);
            *(float4*)(s_in + ci * PLANE_P + r * SROW_P + pc) = v;
        }
    }
    __syncthreads();

    // ---- compute: each thread = 16 pixels x 4 out-channels ----
    const int r  = tid >> 3;            // row within tile, 0..15
    const int j  = tid & 7;             // 16-pixel slab, x = 16j..16j+15
    const int base = r * SROW_P + 20 * j;   // phys(16j) = 20j

    u64 acc[4][8];                      // [co][pixel-pair]
    #pragma unroll
    for (int co = 0; co < 4; co++) {
        const float bv = s_bias[co];
        const u64 bp = pk(bv, bv);
        #pragma unroll
        for (int q = 0; q < 8; q++) acc[co][q] = bp;
    }

    #pragma unroll
    for (int ci = 0; ci < 4; ci++) {
        #pragma unroll
        for (int ky = 0; ky < 3; ky++) {
            const int imm = ci * PLANE_P + ky * SROW_P;   // compile-time
            F4 B, C, B2, C2;
            B.f  = *(const float4*)(s_in + imm + base);
            C.f  = *(const float4*)(s_in + imm + base + 4);
            B2.f = *(const float4*)(s_in + imm + base + 8);
            C2.f = *(const float4*)(s_in + imm + base + 12);

            // outer edges from neighbor lanes (zero at x-boundaries)
            float A = __shfl_up_sync(0xffffffffu, C2.f.w, 1);
            float D = __shfl_down_sync(0xffffffffu, B.f.x, 1);
            if (j == 0) A = 0.0f;
            if (j == 7) D = 0.0f;

            // 17 adjacent pairs of window x(16j-1 .. 16j+16)
            u64 P[17];
            P[0]  = pk(A,      B.f.x);
            P[1]  = B.u.x;
            P[2]  = pk(B.f.y,  B.f.z);
            P[3]  = B.u.y;
            P[4]  = pk(B.f.w,  C.f.x);
            P[5]  = C.u.x;
            P[6]  = pk(C.f.y,  C.f.z);
            P[7]  = C.u.y;
            P[8]  = pk(C.f.w,  B2.f.x);
            P[9]  = B2.u.x;
            P[10] = pk(B2.f.y, B2.f.z);
            P[11] = B2.u.y;
            P[12] = pk(B2.f.w, C2.f.x);
            P[13] = C2.u.x;
            P[14] = pk(C2.f.y, C2.f.z);
            P[15] = C2.u.y;
            P[16] = pk(C2.f.w, D);

            // weights: 6 x LDS.128 uniform broadcast -> [kx][co]
            const ulonglong2* wp = (const ulonglong2*)(s_w + (ci * 9 + ky * 3) * 4);
            ulonglong2 wv[6];
            #pragma unroll
            for (int t = 0; t < 6; t++) wv[t] = wp[t];

            // 96 packed FMAs
            #pragma unroll
            for (int q = 0; q < 8; q++)
                #pragma unroll
                for (int kx = 0; kx < 3; kx++) {
                    const u64 in = P[2 * q + kx];
                    ffma2(acc[0][q], wv[kx * 2 + 0].x, in);
                    ffma2(acc[1][q], wv[kx * 2 + 0].y, in);
                    ffma2(acc[2][q], wv[kx * 2 + 1].x, in);
                    ffma2(acc[3][q], wv[kx * 2 + 1].y, in);
                }
        }
    }

    // ---- store: coalesced 4x STG.128 per co ----
    const int y = y0 + r;
    float* obase = out + (((long long)b * 256 + head) * H + y) * W + (j << 4);
    #pragma unroll
    for (int co = 0; co < 4; co++) {
        ulonglong2* dst = (ulonglong2*)(obase + (long long)co * (64 * PLANE));
        ulonglong2 s0, s1, s2, s3;
        s0.x = acc[co][0]; s0.y = acc[co][1];
        s1.x = acc[co][2]; s1.y = acc[co][3];
        s2.x = acc[co][4]; s2.y = acc[co][5];
        s3.x = acc[co][6]; s3.y = acc[co][7];
        dst[0] = s0;
        dst[1] = s1;
        dst[2] = s2;
        dst[3] = s3;
    }
}

extern "C" void kernel_launch(void* const* d_in, const int* in_sizes, int n_in,
                              void* d_out, int out_size) {
    const float* x    = (const float*)d_in[0];
    const float* w    = (const float*)d_in[1];
    const float* bias = (const float*)d_in[2];
    float* out        = (float*)d_out;
    (void)in_sizes; (void)n_in; (void)out_size;
    cudaFuncSetAttribute(bdconv_kernel,
                         cudaFuncAttributeMaxDynamicSharedMemorySize, SMEM_BYTES);
    bdconv_kernel<<<32 * 64 * 8, THREADS, SMEM_BYTES>>>(x, w, bias, out);
}